// round 7
// baseline (speedup 1.0000x reference)
#include <cuda_runtime.h>
#include <math.h>
#include <stdint.h>

// ---------------------------------------------------------------------------
// Revisit_RDLoss: debiased Sinkhorn divergence over softmax rows, 3 pairs.
//
// Stage 1 (gram_kernel): Z = [exp(teacher); exp(rec)] (32 rows x M).
//   G = Z Z^T + row sums S. 256-thread blocks, 2 per SM, TKI=128 K/iter:
//   load 16 KB fp32 -> exp -> bf16 pack -> SW128-swizzled smem (2 sub-tiles
//   of 32 x 128B), double-buffered, one __syncthreads per iteration.
//   8 warps each own one k16-step: 2 ldmatrix.x4 serve as BOTH A and B
//   fragments (Gram symmetry) -> 8 mma.m16n8k16.bf16.f32 per warp per iter.
//   Block partials (fp32) plain-stored to a per-block slot: no global
//   atomics, no zero kernel.
// Stage 2 (solver_kernel): 3 blocks; each reduces its pair's block partials
//   in fp64, builds C, runs the 60-step eps-scaled Sinkhorn with the exact
//   softmin reformulation -eps*log1p(mean_j expm1(u)) (cubic Taylor, |u|<=1e-2),
//   and the last-finished block writes d_out via an atomic ticket (self-reset).
// ---------------------------------------------------------------------------

#define BROWS 16
#define NTHR  256            // 8 warps
#define BUFB  8192           // bytes per smem buffer (2 sub-tiles x 4096)

__device__ float        g_bgram[304][1056];   // per-block partials: 1024 gram + 32 sums
__device__ double       g_partial[3];
__device__ unsigned int g_ctr;                // zero-init; self-reset each run

// ---- PTX helpers ------------------------------------------------------------
#define LDSM_X4(r0, r1, r2, r3, a)                                          \
    asm volatile("ldmatrix.sync.aligned.x4.m8n8.shared.b16 {%0,%1,%2,%3}, [%4];" \
                 : "=r"(r0), "=r"(r1), "=r"(r2), "=r"(r3) : "r"(a))

#define MMA16816(c, a0, a1, a2, a3, b0, b1)                                 \
    asm volatile("mma.sync.aligned.m16n8k16.row.col.f32.bf16.bf16.f32 "     \
                 "{%0,%1,%2,%3}, {%4,%5,%6,%7}, {%8,%9}, {%0,%1,%2,%3};"    \
                 : "+f"((c)[0]), "+f"((c)[1]), "+f"((c)[2]), "+f"((c)[3])   \
                 : "r"(a0), "r"(a1), "r"(a2), "r"(a3), "r"(b0), "r"(b1))

__device__ __forceinline__ unsigned int pack_bf16x2(float hi, float lo) {
    unsigned int r;
    asm("cvt.rn.bf16x2.f32 %0, %1, %2;" : "=r"(r) : "f"(hi), "f"(lo));
    return r;
}

__device__ __forceinline__ void sts64(unsigned int addr, unsigned int p0, unsigned int p1) {
    asm volatile("st.shared.v2.b32 [%0], {%1, %2};" :: "r"(addr), "r"(p0), "r"(p1));
}

__global__ void __launch_bounds__(NTHR, 2)
gram_kernel(const float* __restrict__ T0, const float* __restrict__ R0, int M0, int nb0,
            const float* __restrict__ T1, const float* __restrict__ R1, int M1, int nb1,
            const float* __restrict__ T2, const float* __restrict__ R2, int M2, int nb2)
{
    __shared__ __align__(16) char smem_raw[2 * BUFB];
    const uint32_t sbase = (uint32_t)__cvta_generic_to_shared(smem_raw);

    const int tid  = threadIdx.x;
    const int wid  = tid >> 5;
    const int lane = tid & 31;

    // --- pick pair ---
    const float *T, *R; int M, lb, nb;
    int b = blockIdx.x;
    if (b < nb0)            { T = T0; R = R0; M = M0; lb = b;             nb = nb0; }
    else if (b < nb0 + nb1) { T = T1; R = R1; M = M1; lb = b - nb0;       nb = nb1; }
    else                    { T = T2; R = R2; M = M2; lb = b - nb0 - nb1; nb = nb2; }

    // --- loader mapping: warp w covers rows {r0, r0+1, r0+4, r0+5} so the
    //     swizzled STS.64s hit both 64B halves -> 2-phase (conflict-free). ---
    const int row = ((wid >> 1) << 3) + ((wid & 1) << 1)
                  + ((lane >> 3) & 1) + ((lane >> 4) << 2);
    const int c4  = lane & 7;
    const float* rbase = (row < BROWS) ? (T + (size_t)row * (size_t)M)
                                       : (R + (size_t)(row - BROWS) * (size_t)M);
    const float4* g4 = (const float4*)rbase + c4;

    uint32_t stsA[4];
#pragma unroll
    for (int t = 0; t < 4; t++) {
        int inb = c4 * 8 + 64 * (t & 1);
        int off = row * 128 + inb;
        stsA[t] = sbase + (t >> 1) * 4096 + (off ^ ((row & 7) << 4));
    }

    // --- ldmatrix addresses: warp wid owns k16-step wid (k in [16w,16w+16)) ---
    const int q  = wid >> 2;            // sub-tile (k 0-63 / 64-127)
    const int ko = (wid & 3) * 32;      // byte offset of k16 within 128B row
    const int kb = (lane & 16);         // klo / khi 8x8 matrices
    const int rw = lane & 15;
    int oA = rw * 128 + ko + kb;        oA = q * 4096 + (oA ^ ((rw & 7) << 4));
    int rB = rw + 16;
    int oB = rB * 128 + ko + kb;        oB = q * 4096 + (oB ^ ((rB & 7) << 4));
    const uint32_t lds00 = sbase + oA, lds01 = sbase + oB;        // buf0
    const uint32_t lds10 = lds00 + BUFB, lds11 = lds01 + BUFB;    // buf1

    float acc[8][4];
#pragma unroll
    for (int i = 0; i < 8; i++)
#pragma unroll
        for (int jj = 0; jj < 4; jj++) acc[i][jj] = 0.f;
    float rsum = 0.f;

    const int niter = M >> 7;                       // TKI = 128
    const int cnt = (niter - lb + nb - 1) / nb;

    float4 vA[4], vB[4];
#pragma unroll
    for (int t = 0; t < 4; t++)
        vA[t] = __ldg(g4 + (size_t)lb * 32 + t * 8);
    if (cnt > 1) {
#pragma unroll
        for (int t = 0; t < 4; t++)
            vB[t] = __ldg(g4 + (size_t)(lb + nb) * 32 + t * 8);
    }

    auto stage = [&](float4* v, uint32_t bofs) {
#pragma unroll
        for (int t = 0; t < 4; t++) {
            float e0 = __expf(v[t].x), e1 = __expf(v[t].y);
            float e2 = __expf(v[t].z), e3 = __expf(v[t].w);
            rsum += (e0 + e1) + (e2 + e3);
            sts64(stsA[t] + bofs, pack_bf16x2(e1, e0), pack_bf16x2(e3, e2));
        }
    };
    auto mma_phase = [&](uint32_t a0addr, uint32_t a1addr) {
        uint32_t L0[4], L1[4];
        LDSM_X4(L0[0], L0[1], L0[2], L0[3], a0addr);   // rows 0-15
        LDSM_X4(L1[0], L1[1], L1[2], L1[3], a1addr);   // rows 16-31
        MMA16816(acc[0], L0[0], L0[1], L0[2], L0[3], L0[0], L0[2]);  // m0-15 n0-7
        MMA16816(acc[1], L0[0], L0[1], L0[2], L0[3], L0[1], L0[3]);  // n8-15
        MMA16816(acc[2], L0[0], L0[1], L0[2], L0[3], L1[0], L1[2]);  // n16-23
        MMA16816(acc[3], L0[0], L0[1], L0[2], L0[3], L1[1], L1[3]);  // n24-31
        MMA16816(acc[4], L1[0], L1[1], L1[2], L1[3], L0[0], L0[2]);  // m16-31
        MMA16816(acc[5], L1[0], L1[1], L1[2], L1[3], L0[1], L0[3]);
        MMA16816(acc[6], L1[0], L1[1], L1[2], L1[3], L1[0], L1[2]);
        MMA16816(acc[7], L1[0], L1[1], L1[2], L1[3], L1[1], L1[3]);
    };

    int j = 0;
    while (true) {
        stage(vA, 0);
        {
            int pf = lb + (j + 2) * nb;
            if (pf < niter) {
#pragma unroll
                for (int t = 0; t < 4; t++)
                    vA[t] = __ldg(g4 + (size_t)pf * 32 + t * 8);
            }
        }
        __syncthreads();
        mma_phase(lds00, lds01);
        j++; if (j >= cnt) break;

        stage(vB, BUFB);
        {
            int pf = lb + (j + 2) * nb;
            if (pf < niter) {
#pragma unroll
                for (int t = 0; t < 4; t++)
                    vB[t] = __ldg(g4 + (size_t)pf * 32 + t * 8);
            }
        }
        __syncthreads();
        mma_phase(lds10, lds11);
        j++; if (j >= cnt) break;
    }

    // --- block-level combine (reuse staging smem), then plain-store slot ---
    __syncthreads();
    float* gc = (float*)smem_raw;       // [32][33]
    float* rs = gc + 32 * 33;           // [32]
    for (int i = tid; i < 32 * 33 + 32; i += NTHR) gc[i] = 0.f;
    __syncthreads();

    {
        const int fr = lane >> 2;
        const int fc = 2 * (lane & 3);
#pragma unroll
        for (int mi = 0; mi < 2; mi++)
#pragma unroll
            for (int nt = 0; nt < 4; nt++) {
                float* a = acc[mi * 4 + nt];
                int r = mi * 16 + fr;
                int c = nt * 8 + fc;
                atomicAdd(&gc[r * 33 + c],           a[0]);
                atomicAdd(&gc[r * 33 + c + 1],       a[1]);
                atomicAdd(&gc[(r + 8) * 33 + c],     a[2]);
                atomicAdd(&gc[(r + 8) * 33 + c + 1], a[3]);
            }
        float s = rsum;
        s += __shfl_xor_sync(0xffffffffu, s, 1);
        s += __shfl_xor_sync(0xffffffffu, s, 2);
        s += __shfl_xor_sync(0xffffffffu, s, 4);
        if ((lane & 7) == 0) atomicAdd(&rs[row], s);
    }
    __syncthreads();

    float* slot = g_bgram[blockIdx.x];
    for (int i = tid; i < 1024; i += NTHR)
        slot[i] = gc[(i >> 5) * 33 + (i & 31)];
    if (tid < 32) slot[1024 + tid] = rs[tid];
}

// ---------------------------------------------------------------------------
// Sinkhorn solver: 3 blocks (one per pair), 1024 threads = 4 softmins x 16x16.
// Reduces per-block gram partials in fp64, then runs the scan.
// ---------------------------------------------------------------------------
__global__ void __launch_bounds__(1024, 1)
solver_kernel(float* out, int nb0, int nb1, int nb2)
{
    const int p = blockIdx.x;
    __shared__ double sG[32][32];
    __shared__ double sS[32];
    __shared__ float Cxy[16][16], Cxx[16][16], Cyy[16][16];
    __shared__ float pot[2][4][16];
    __shared__ float fin[4][16];
    __shared__ float epss[60];

    const int tid = threadIdx.x;
    const int q = tid >> 8;
    const int i = (tid >> 4) & 15;
    const int j = tid & 15;

    const int off  = (p == 0) ? 0 : ((p == 1) ? nb0 : nb0 + nb1);
    const int cntb = (p == 0) ? nb0 : ((p == 1) ? nb1 : nb2);

    // --- reduce block partials (fp64) ---
    {
        double a = 0.0;
#pragma unroll 4
        for (int b2 = 0; b2 < cntb; b2++) a += (double)g_bgram[off + b2][tid];
        sG[tid >> 5][tid & 31] = a;
        if (tid < 32) {
            double s2 = 0.0;
#pragma unroll 4
            for (int b2 = 0; b2 < cntb; b2++) s2 += (double)g_bgram[off + b2][1024 + tid];
            sS[tid] = s2;
        }
    }
    if (tid < 60) {
        double e = pow(0.9025, (double)tid);
        epss[tid] = (float)fmax(e, 0.0025);
    }
    if (tid < 64) pot[0][tid >> 4][tid & 15] = 0.f;
    __syncthreads();

    if (tid < 256) {
        int ii = tid >> 4, jj = tid & 15;
        double Si  = sS[ii],      Sj  = sS[jj];
        double Syi = sS[16 + ii], Syj = sS[16 + jj];
        double a2i = sG[ii][ii] / (Si * Si);
        double a2j = sG[jj][jj] / (Sj * Sj);
        double b2i = sG[16 + ii][16 + ii] / (Syi * Syi);
        double b2j = sG[16 + jj][16 + jj] / (Syj * Syj);
        double dxy = sG[ii][16 + jj] / (Si * Syj);
        int lo = min(ii, jj), hi = max(ii, jj);
        double dxx = sG[lo][hi]           / (Si * Sj);
        double dyy = sG[16 + lo][16 + hi] / (Syi * Syj);
        Cxy[ii][jj] = (float)(0.5 * (a2i + b2j) - dxy);
        Cxx[ii][jj] = (float)(0.5 * (a2i + a2j) - dxx);
        Cyy[ii][jj] = (float)(0.5 * (b2i + b2j) - dyy);
    }
    __syncthreads();

    int cur = 0;
    for (int s = 0; s < 60; s++) {
        float eps = epss[s];
        float inv_eps = 1.0f / eps;
        float h, Cv, old;
        if (q == 0)      { h = pot[cur][1][j]; Cv = Cxy[i][j]; old = pot[cur][0][i]; }
        else if (q == 1) { h = pot[cur][0][j]; Cv = Cxy[j][i]; old = pot[cur][1][i]; }
        else if (q == 2) { h = pot[cur][2][j]; Cv = Cxx[i][j]; old = pot[cur][2][i]; }
        else             { h = pot[cur][3][j]; Cv = Cyy[i][j]; old = pot[cur][3][i]; }
        float u = (h - Cv) * inv_eps;
        float t = u * fmaf(u, fmaf(u, 0.16666667f, 0.5f), 1.0f);   // expm1
        t += __shfl_xor_sync(0xffffffffu, t, 1);
        t += __shfl_xor_sync(0xffffffffu, t, 2);
        t += __shfl_xor_sync(0xffffffffu, t, 4);
        t += __shfl_xor_sync(0xffffffffu, t, 8);
        if (j == 0) {
            float m = t * 0.0625f;
            float l = m * fmaf(m, fmaf(m, 0.33333333f, -0.5f), 1.0f);  // log1p
            pot[cur ^ 1][q][i] = 0.5f * (old - eps * l);
        }
        __syncthreads();
        cur ^= 1;
    }

    {
        const float eps = 0.0025f;
        const float inv_eps = 1.0f / eps;
        float h, Cv;
        if (q == 0)      { h = pot[cur][1][j]; Cv = Cxy[i][j]; }
        else if (q == 1) { h = pot[cur][0][j]; Cv = Cxy[j][i]; }
        else if (q == 2) { h = pot[cur][2][j]; Cv = Cxx[i][j]; }
        else             { h = pot[cur][3][j]; Cv = Cyy[i][j]; }
        float u = (h - Cv) * inv_eps;
        float t = u * fmaf(u, fmaf(u, 0.16666667f, 0.5f), 1.0f);
        t += __shfl_xor_sync(0xffffffffu, t, 1);
        t += __shfl_xor_sync(0xffffffffu, t, 2);
        t += __shfl_xor_sync(0xffffffffu, t, 4);
        t += __shfl_xor_sync(0xffffffffu, t, 8);
        if (j == 0) {
            float m = t * 0.0625f;
            float l = m * fmaf(m, fmaf(m, 0.33333333f, -0.5f), 1.0f);
            fin[q][i] = -eps * l;
        }
        __syncthreads();
    }

    if (tid == 0) {
        double acc2 = 0.0;
        for (int ii = 0; ii < 16; ii++)
            acc2 += ((double)fin[0][ii] - (double)fin[2][ii])
                  + ((double)fin[1][ii] - (double)fin[3][ii]);
        g_partial[p] = acc2 / 48.0;          // mean over 16, /3 pairs
        __threadfence();
        unsigned int tk = atomicAdd(&g_ctr, 1);
        if (tk == 2) {
            out[0] = (float)(g_partial[0] + g_partial[1] + g_partial[2]);
            g_ctr = 0;                       // self-reset for graph replay
        }
    }
}

// ---------------------------------------------------------------------------
extern "C" void kernel_launch(void* const* d_in, const int* in_sizes, int n_in,
                              void* d_out, int out_size)
{
    (void)out_size;
    // Pair the 6 inputs by element count (divergence is symmetric in (x, y)).
    int idx[6] = {0, 1, 2, 3, 4, 5};
    int n = (n_in < 6) ? n_in : 6;
    for (int a = 0; a < n; a++)
        for (int b = a + 1; b < n; b++)
            if (in_sizes[idx[b]] > in_sizes[idx[a]]) {
                int tmp = idx[a]; idx[a] = idx[b]; idx[b] = tmp;
            }

    const float* T[3]; const float* R[3]; int M[3]; int nb[3];
    for (int p = 0; p < 3; p++) {
        T[p] = (const float*)d_in[idx[2 * p]];
        R[p] = (const float*)d_in[idx[2 * p + 1]];
        M[p] = in_sizes[idx[2 * p]] / BROWS;
        int iters = M[p] >> 7;                 // TKI = 128
        nb[p] = (iters + 48) / 49;             // ~49 iters/block, <=296 blocks total
        if (nb[p] < 1) nb[p] = 1;
        if (nb[p] > iters) nb[p] = iters;
        if (nb[p] > 100) { /* cap safety for slot array */ }
    }
    // slot-array safety: total blocks must fit g_bgram (304 slots)
    int tot = nb[0] + nb[1] + nb[2];
    if (tot > 304) { nb[0] -= (tot - 304); if (nb[0] < 1) nb[0] = 1; tot = nb[0] + nb[1] + nb[2]; }

    gram_kernel<<<tot, NTHR>>>(
        T[0], R[0], M[0], nb[0],
        T[1], R[1], M[1], nb[1],
        T[2], R[2], M[2], nb[2]);
    solver_kernel<<<3, 1024>>>((float*)d_out, nb[0], nb[1], nb[2]);
}

// round 8
// speedup vs baseline: 1.0114x; 1.0114x over previous
#include <cuda_runtime.h>
#include <math.h>
#include <stdint.h>

// ---------------------------------------------------------------------------
// Revisit_RDLoss: debiased Sinkhorn divergence over softmax rows, 3 pairs.
//
// Stage 1 (gram_kernel): Z = [exp(teacher); exp(rec)] (32 rows x M).
//   G = Z Z^T + row sums S. 256-thread blocks, 2 per SM, TKI=128 K/iter:
//   load 16 KB fp32 -> exp -> bf16 pack -> SW128-swizzled smem (2 sub-tiles
//   of 32 x 128B), double-buffered, one __syncthreads per iteration.
//   8 warps each own one k16-step: 2 ldmatrix.x4 serve as BOTH A and B
//   fragments (Gram symmetry) -> 8 mma.m16n8k16.bf16.f32 per warp per iter.
//   Block partials (fp32) plain-stored to a per-block slot: no global
//   atomics, no zero kernel.  (Measured at the HBM roofline, ~28 us.)
// Stage 2 (solver_kernel): 3 blocks; each reduces its pair's block partials
//   in fp64 with 8-way MLP (independent accumulators -> 8 loads in flight;
//   the R7 version used a serial chain and took 161 us on 3 idle SMs),
//   builds C, runs the 60-step eps-scaled Sinkhorn with the exact softmin
//   reformulation -eps*log1p(mean_j expm1(u)) (cubic Taylor, |u|<=1e-2),
//   and the last-finished block writes d_out via an atomic ticket (self-reset).
// ---------------------------------------------------------------------------

#define BROWS 16
#define NTHR  256            // 8 warps
#define BUFB  8192           // bytes per smem buffer (2 sub-tiles x 4096)

__device__ float        g_bgram[304][1056];   // per-block partials: 1024 gram + 32 sums
__device__ double       g_partial[3];
__device__ unsigned int g_ctr;                // zero-init; self-reset each run

// ---- PTX helpers ------------------------------------------------------------
#define LDSM_X4(r0, r1, r2, r3, a)                                          \
    asm volatile("ldmatrix.sync.aligned.x4.m8n8.shared.b16 {%0,%1,%2,%3}, [%4];" \
                 : "=r"(r0), "=r"(r1), "=r"(r2), "=r"(r3) : "r"(a))

#define MMA16816(c, a0, a1, a2, a3, b0, b1)                                 \
    asm volatile("mma.sync.aligned.m16n8k16.row.col.f32.bf16.bf16.f32 "     \
                 "{%0,%1,%2,%3}, {%4,%5,%6,%7}, {%8,%9}, {%0,%1,%2,%3};"    \
                 : "+f"((c)[0]), "+f"((c)[1]), "+f"((c)[2]), "+f"((c)[3])   \
                 : "r"(a0), "r"(a1), "r"(a2), "r"(a3), "r"(b0), "r"(b1))

__device__ __forceinline__ unsigned int pack_bf16x2(float hi, float lo) {
    unsigned int r;
    asm("cvt.rn.bf16x2.f32 %0, %1, %2;" : "=r"(r) : "f"(hi), "f"(lo));
    return r;
}

__device__ __forceinline__ void sts64(unsigned int addr, unsigned int p0, unsigned int p1) {
    asm volatile("st.shared.v2.b32 [%0], {%1, %2};" :: "r"(addr), "r"(p0), "r"(p1));
}

__global__ void __launch_bounds__(NTHR, 2)
gram_kernel(const float* __restrict__ T0, const float* __restrict__ R0, int M0, int nb0,
            const float* __restrict__ T1, const float* __restrict__ R1, int M1, int nb1,
            const float* __restrict__ T2, const float* __restrict__ R2, int M2, int nb2)
{
    __shared__ __align__(16) char smem_raw[2 * BUFB];
    const uint32_t sbase = (uint32_t)__cvta_generic_to_shared(smem_raw);

    const int tid  = threadIdx.x;
    const int wid  = tid >> 5;
    const int lane = tid & 31;

    // --- pick pair ---
    const float *T, *R; int M, lb, nb;
    int b = blockIdx.x;
    if (b < nb0)            { T = T0; R = R0; M = M0; lb = b;             nb = nb0; }
    else if (b < nb0 + nb1) { T = T1; R = R1; M = M1; lb = b - nb0;       nb = nb1; }
    else                    { T = T2; R = R2; M = M2; lb = b - nb0 - nb1; nb = nb2; }

    // --- loader mapping: warp w covers rows {r0, r0+1, r0+4, r0+5} so the
    //     swizzled STS.64s hit both 64B halves -> 2-phase (conflict-free). ---
    const int row = ((wid >> 1) << 3) + ((wid & 1) << 1)
                  + ((lane >> 3) & 1) + ((lane >> 4) << 2);
    const int c4  = lane & 7;
    const float* rbase = (row < BROWS) ? (T + (size_t)row * (size_t)M)
                                       : (R + (size_t)(row - BROWS) * (size_t)M);
    const float4* g4 = (const float4*)rbase + c4;

    uint32_t stsA[4];
#pragma unroll
    for (int t = 0; t < 4; t++) {
        int inb = c4 * 8 + 64 * (t & 1);
        int off = row * 128 + inb;
        stsA[t] = sbase + (t >> 1) * 4096 + (off ^ ((row & 7) << 4));
    }

    // --- ldmatrix addresses: warp wid owns k16-step wid (k in [16w,16w+16)) ---
    const int q  = wid >> 2;            // sub-tile (k 0-63 / 64-127)
    const int ko = (wid & 3) * 32;      // byte offset of k16 within 128B row
    const int kb = (lane & 16);         // klo / khi 8x8 matrices
    const int rw = lane & 15;
    int oA = rw * 128 + ko + kb;        oA = q * 4096 + (oA ^ ((rw & 7) << 4));
    int rB = rw + 16;
    int oB = rB * 128 + ko + kb;        oB = q * 4096 + (oB ^ ((rB & 7) << 4));
    const uint32_t lds00 = sbase + oA, lds01 = sbase + oB;        // buf0
    const uint32_t lds10 = lds00 + BUFB, lds11 = lds01 + BUFB;    // buf1

    float acc[8][4];
#pragma unroll
    for (int i = 0; i < 8; i++)
#pragma unroll
        for (int jj = 0; jj < 4; jj++) acc[i][jj] = 0.f;
    float rsum = 0.f;

    const int niter = M >> 7;                       // TKI = 128
    const int cnt = (niter - lb + nb - 1) / nb;

    float4 vA[4], vB[4];
#pragma unroll
    for (int t = 0; t < 4; t++)
        vA[t] = __ldg(g4 + (size_t)lb * 32 + t * 8);
    if (cnt > 1) {
#pragma unroll
        for (int t = 0; t < 4; t++)
            vB[t] = __ldg(g4 + (size_t)(lb + nb) * 32 + t * 8);
    }

    auto stage = [&](float4* v, uint32_t bofs) {
#pragma unroll
        for (int t = 0; t < 4; t++) {
            float e0 = __expf(v[t].x), e1 = __expf(v[t].y);
            float e2 = __expf(v[t].z), e3 = __expf(v[t].w);
            rsum += (e0 + e1) + (e2 + e3);
            sts64(stsA[t] + bofs, pack_bf16x2(e1, e0), pack_bf16x2(e3, e2));
        }
    };
    auto mma_phase = [&](uint32_t a0addr, uint32_t a1addr) {
        uint32_t L0[4], L1[4];
        LDSM_X4(L0[0], L0[1], L0[2], L0[3], a0addr);   // rows 0-15
        LDSM_X4(L1[0], L1[1], L1[2], L1[3], a1addr);   // rows 16-31
        MMA16816(acc[0], L0[0], L0[1], L0[2], L0[3], L0[0], L0[2]);  // m0-15 n0-7
        MMA16816(acc[1], L0[0], L0[1], L0[2], L0[3], L0[1], L0[3]);  // n8-15
        MMA16816(acc[2], L0[0], L0[1], L0[2], L0[3], L1[0], L1[2]);  // n16-23
        MMA16816(acc[3], L0[0], L0[1], L0[2], L0[3], L1[1], L1[3]);  // n24-31
        MMA16816(acc[4], L1[0], L1[1], L1[2], L1[3], L0[0], L0[2]);  // m16-31
        MMA16816(acc[5], L1[0], L1[1], L1[2], L1[3], L0[1], L0[3]);
        MMA16816(acc[6], L1[0], L1[1], L1[2], L1[3], L1[0], L1[2]);
        MMA16816(acc[7], L1[0], L1[1], L1[2], L1[3], L1[1], L1[3]);
    };

    int j = 0;
    while (true) {
        stage(vA, 0);
        {
            int pf = lb + (j + 2) * nb;
            if (pf < niter) {
#pragma unroll
                for (int t = 0; t < 4; t++)
                    vA[t] = __ldg(g4 + (size_t)pf * 32 + t * 8);
            }
        }
        __syncthreads();
        mma_phase(lds00, lds01);
        j++; if (j >= cnt) break;

        stage(vB, BUFB);
        {
            int pf = lb + (j + 2) * nb;
            if (pf < niter) {
#pragma unroll
                for (int t = 0; t < 4; t++)
                    vB[t] = __ldg(g4 + (size_t)pf * 32 + t * 8);
            }
        }
        __syncthreads();
        mma_phase(lds10, lds11);
        j++; if (j >= cnt) break;
    }

    // --- block-level combine (reuse staging smem), then plain-store slot ---
    __syncthreads();
    float* gc = (float*)smem_raw;       // [32][33]
    float* rs = gc + 32 * 33;           // [32]
    for (int i = tid; i < 32 * 33 + 32; i += NTHR) gc[i] = 0.f;
    __syncthreads();

    {
        const int fr = lane >> 2;
        const int fc = 2 * (lane & 3);
#pragma unroll
        for (int mi = 0; mi < 2; mi++)
#pragma unroll
            for (int nt = 0; nt < 4; nt++) {
                float* a = acc[mi * 4 + nt];
                int r = mi * 16 + fr;
                int c = nt * 8 + fc;
                atomicAdd(&gc[r * 33 + c],           a[0]);
                atomicAdd(&gc[r * 33 + c + 1],       a[1]);
                atomicAdd(&gc[(r + 8) * 33 + c],     a[2]);
                atomicAdd(&gc[(r + 8) * 33 + c + 1], a[3]);
            }
        float s = rsum;
        s += __shfl_xor_sync(0xffffffffu, s, 1);
        s += __shfl_xor_sync(0xffffffffu, s, 2);
        s += __shfl_xor_sync(0xffffffffu, s, 4);
        if ((lane & 7) == 0) atomicAdd(&rs[row], s);
    }
    __syncthreads();

    float* slot = g_bgram[blockIdx.x];
    for (int i = tid; i < 1024; i += NTHR)
        slot[i] = gc[(i >> 5) * 33 + (i & 31)];
    if (tid < 32) slot[1024 + tid] = rs[tid];
}

// ---------------------------------------------------------------------------
// Sinkhorn solver: 3 blocks (one per pair), 1024 threads = 4 softmins x 16x16.
// Cross-block partial reduction with 8 independent fp64 accumulators (MLP=8;
// warp 0 carries the 32 row-sum entries in the same loop -> 16 in flight).
// ---------------------------------------------------------------------------
__global__ void __launch_bounds__(1024, 1)
solver_kernel(float* out, int nb0, int nb1, int nb2)
{
    const int p = blockIdx.x;
    __shared__ double sG[32][32];
    __shared__ double sS[32];
    __shared__ float Cxy[16][16], Cxx[16][16], Cyy[16][16];
    __shared__ float pot[2][4][16];
    __shared__ float fin[4][16];
    __shared__ float epss[60];

    const int tid = threadIdx.x;
    const int q = tid >> 8;
    const int i = (tid >> 4) & 15;
    const int j = tid & 15;

    const int off  = (p == 0) ? 0 : ((p == 1) ? nb0 : nb0 + nb1);
    const int cntb = (p == 0) ? nb0 : ((p == 1) ? nb1 : nb2);

    // --- reduce block partials: 8-way independent accumulators (MLP) ---
    {
        const bool hasS = (tid < 32);
        double a0 = 0.0, a1 = 0.0, a2 = 0.0, a3 = 0.0;
        double a4 = 0.0, a5 = 0.0, a6 = 0.0, a7 = 0.0;
        double s0 = 0.0, s1 = 0.0, s2 = 0.0, s3 = 0.0;
        double s4 = 0.0, s5 = 0.0, s6 = 0.0, s7 = 0.0;
        int b2 = 0;
        for (; b2 + 8 <= cntb; b2 += 8) {
            const float* r0 = g_bgram[off + b2];
            a0 += (double)__ldg(r0 + tid);
            a1 += (double)__ldg(r0 + 1056 + tid);
            a2 += (double)__ldg(r0 + 2 * 1056 + tid);
            a3 += (double)__ldg(r0 + 3 * 1056 + tid);
            a4 += (double)__ldg(r0 + 4 * 1056 + tid);
            a5 += (double)__ldg(r0 + 5 * 1056 + tid);
            a6 += (double)__ldg(r0 + 6 * 1056 + tid);
            a7 += (double)__ldg(r0 + 7 * 1056 + tid);
            if (hasS) {
                const float* rsrc = r0 + 1024 + tid;
                s0 += (double)__ldg(rsrc);
                s1 += (double)__ldg(rsrc + 1056);
                s2 += (double)__ldg(rsrc + 2 * 1056);
                s3 += (double)__ldg(rsrc + 3 * 1056);
                s4 += (double)__ldg(rsrc + 4 * 1056);
                s5 += (double)__ldg(rsrc + 5 * 1056);
                s6 += (double)__ldg(rsrc + 6 * 1056);
                s7 += (double)__ldg(rsrc + 7 * 1056);
            }
        }
        for (; b2 < cntb; b2++) {
            a0 += (double)__ldg(&g_bgram[off + b2][tid]);
            if (hasS) s0 += (double)__ldg(&g_bgram[off + b2][1024 + tid]);
        }
        sG[tid >> 5][tid & 31] =
            ((a0 + a1) + (a2 + a3)) + ((a4 + a5) + (a6 + a7));
        if (hasS)
            sS[tid] = ((s0 + s1) + (s2 + s3)) + ((s4 + s5) + (s6 + s7));
    }
    if (tid < 60) {
        double e = pow(0.9025, (double)tid);
        epss[tid] = (float)fmax(e, 0.0025);
    }
    if (tid < 64) pot[0][tid >> 4][tid & 15] = 0.f;
    __syncthreads();

    if (tid < 256) {
        int ii = tid >> 4, jj = tid & 15;
        double Si  = sS[ii],      Sj  = sS[jj];
        double Syi = sS[16 + ii], Syj = sS[16 + jj];
        double a2i = sG[ii][ii] / (Si * Si);
        double a2j = sG[jj][jj] / (Sj * Sj);
        double b2i = sG[16 + ii][16 + ii] / (Syi * Syi);
        double b2j = sG[16 + jj][16 + jj] / (Syj * Syj);
        double dxy = sG[ii][16 + jj] / (Si * Syj);
        int lo = min(ii, jj), hi = max(ii, jj);
        double dxx = sG[lo][hi]           / (Si * Sj);
        double dyy = sG[16 + lo][16 + hi] / (Syi * Syj);
        Cxy[ii][jj] = (float)(0.5 * (a2i + b2j) - dxy);
        Cxx[ii][jj] = (float)(0.5 * (a2i + a2j) - dxx);
        Cyy[ii][jj] = (float)(0.5 * (b2i + b2j) - dyy);
    }
    __syncthreads();

    int cur = 0;
    for (int s = 0; s < 60; s++) {
        float eps = epss[s];
        float inv_eps = 1.0f / eps;
        float h, Cv, old;
        if (q == 0)      { h = pot[cur][1][j]; Cv = Cxy[i][j]; old = pot[cur][0][i]; }
        else if (q == 1) { h = pot[cur][0][j]; Cv = Cxy[j][i]; old = pot[cur][1][i]; }
        else if (q == 2) { h = pot[cur][2][j]; Cv = Cxx[i][j]; old = pot[cur][2][i]; }
        else             { h = pot[cur][3][j]; Cv = Cyy[i][j]; old = pot[cur][3][i]; }
        float u = (h - Cv) * inv_eps;
        float t = u * fmaf(u, fmaf(u, 0.16666667f, 0.5f), 1.0f);   // expm1
        t += __shfl_xor_sync(0xffffffffu, t, 1);
        t += __shfl_xor_sync(0xffffffffu, t, 2);
        t += __shfl_xor_sync(0xffffffffu, t, 4);
        t += __shfl_xor_sync(0xffffffffu, t, 8);
        if (j == 0) {
            float m = t * 0.0625f;
            float l = m * fmaf(m, fmaf(m, 0.33333333f, -0.5f), 1.0f);  // log1p
            pot[cur ^ 1][q][i] = 0.5f * (old - eps * l);
        }
        __syncthreads();
        cur ^= 1;
    }

    {
        const float eps = 0.0025f;
        const float inv_eps = 1.0f / eps;
        float h, Cv;
        if (q == 0)      { h = pot[cur][1][j]; Cv = Cxy[i][j]; }
        else if (q == 1) { h = pot[cur][0][j]; Cv = Cxy[j][i]; }
        else if (q == 2) { h = pot[cur][2][j]; Cv = Cxx[i][j]; }
        else             { h = pot[cur][3][j]; Cv = Cyy[i][j]; }
        float u = (h - Cv) * inv_eps;
        float t = u * fmaf(u, fmaf(u, 0.16666667f, 0.5f), 1.0f);
        t += __shfl_xor_sync(0xffffffffu, t, 1);
        t += __shfl_xor_sync(0xffffffffu, t, 2);
        t += __shfl_xor_sync(0xffffffffu, t, 4);
        t += __shfl_xor_sync(0xffffffffu, t, 8);
        if (j == 0) {
            float m = t * 0.0625f;
            float l = m * fmaf(m, fmaf(m, 0.33333333f, -0.5f), 1.0f);
            fin[q][i] = -eps * l;
        }
        __syncthreads();
    }

    if (tid == 0) {
        double acc2 = 0.0;
        for (int ii = 0; ii < 16; ii++)
            acc2 += ((double)fin[0][ii] - (double)fin[2][ii])
                  + ((double)fin[1][ii] - (double)fin[3][ii]);
        g_partial[p] = acc2 / 48.0;          // mean over 16, /3 pairs
        __threadfence();
        unsigned int tk = atomicAdd(&g_ctr, 1);
        if (tk == 2) {
            out[0] = (float)(g_partial[0] + g_partial[1] + g_partial[2]);
            g_ctr = 0;                       // self-reset for graph replay
        }
    }
}

// ---------------------------------------------------------------------------
extern "C" void kernel_launch(void* const* d_in, const int* in_sizes, int n_in,
                              void* d_out, int out_size)
{
    (void)out_size;
    // Pair the 6 inputs by element count (divergence is symmetric in (x, y)).
    int idx[6] = {0, 1, 2, 3, 4, 5};
    int n = (n_in < 6) ? n_in : 6;
    for (int a = 0; a < n; a++)
        for (int b = a + 1; b < n; b++)
            if (in_sizes[idx[b]] > in_sizes[idx[a]]) {
                int tmp = idx[a]; idx[a] = idx[b]; idx[b] = tmp;
            }

    const float* T[3]; const float* R[3]; int M[3]; int nb[3];
    for (int p = 0; p < 3; p++) {
        T[p] = (const float*)d_in[idx[2 * p]];
        R[p] = (const float*)d_in[idx[2 * p + 1]];
        M[p] = in_sizes[idx[2 * p]] / BROWS;
        int iters = M[p] >> 7;                 // TKI = 128
        nb[p] = (iters + 48) / 49;             // ~49 iters/block, <=296 blocks total
        if (nb[p] < 1) nb[p] = 1;
        if (nb[p] > iters) nb[p] = iters;
    }
    // slot-array safety: total blocks must fit g_bgram (304 slots)
    int tot = nb[0] + nb[1] + nb[2];
    if (tot > 304) { nb[0] -= (tot - 304); if (nb[0] < 1) nb[0] = 1; tot = nb[0] + nb[1] + nb[2]; }

    gram_kernel<<<tot, NTHR>>>(
        T[0], R[0], M[0], nb[0],
        T[1], R[1], M[1], nb[1],
        T[2], R[2], M[2], nb[2]);
    solver_kernel<<<3, 1024>>>((float*)d_out, nb[0], nb[1], nb[2]);
}

// round 9
// speedup vs baseline: 2.2861x; 2.2603x over previous
#include <cuda_runtime.h>
#include <math.h>
#include <stdint.h>

// ---------------------------------------------------------------------------
// Revisit_RDLoss: debiased Sinkhorn divergence over softmax rows, 3 pairs.
//
// Stage 1 (gram_kernel): Z = [exp(teacher); exp(rec)] (32 rows x M).
//   G = Z Z^T + row sums S. 256-thread blocks, 2 per SM, TKI=128 K/iter:
//   load 16 KB fp32 -> exp -> bf16 pack -> SW128-swizzled smem (2 sub-tiles
//   of 32 x 128B), double-buffered, one __syncthreads per iteration.
//   8 warps each own one k16-step: 2 ldmatrix.x4 serve as BOTH A and B
//   fragments (Gram symmetry) -> 8 mma.m16n8k16.bf16.f32 per warp per iter.
//   Block partials (fp32) plain-stored to a per-block slot. (At HBM roofline.)
// Stage 2 (solver_kernel): 3 blocks; each reduces its pair's block partials
//   in FP32 (R7/R8 reduced in fp64: 355k FP64-pipe ops on one SM at ~2/cyc
//   = ~100us -- the hidden bottleneck; fp32 partial sums err ~3e-7 rel,
//   negligible vs the 1e-4 bf16 gram error). fp64 is used only for the
//   C-matrix build (real cancellation). Then the 60-step eps-scaled Sinkhorn
//   with softmin = -eps*log1p(mean_j expm1(u)) via cubic Taylor (|u|<=1e-2),
//   and the last-finished block writes d_out via an atomic ticket (self-reset).
// ---------------------------------------------------------------------------

#define BROWS 16
#define NTHR  256            // 8 warps
#define BUFB  8192           // bytes per smem buffer (2 sub-tiles x 4096)

__device__ float        g_bgram[304][1056];   // per-block partials: 1024 gram + 32 sums
__device__ double       g_partial[3];
__device__ unsigned int g_ctr;                // zero-init; self-reset each run

// ---- PTX helpers ------------------------------------------------------------
#define LDSM_X4(r0, r1, r2, r3, a)                                          \
    asm volatile("ldmatrix.sync.aligned.x4.m8n8.shared.b16 {%0,%1,%2,%3}, [%4];" \
                 : "=r"(r0), "=r"(r1), "=r"(r2), "=r"(r3) : "r"(a))

#define MMA16816(c, a0, a1, a2, a3, b0, b1)                                 \
    asm volatile("mma.sync.aligned.m16n8k16.row.col.f32.bf16.bf16.f32 "     \
                 "{%0,%1,%2,%3}, {%4,%5,%6,%7}, {%8,%9}, {%0,%1,%2,%3};"    \
                 : "+f"((c)[0]), "+f"((c)[1]), "+f"((c)[2]), "+f"((c)[3])   \
                 : "r"(a0), "r"(a1), "r"(a2), "r"(a3), "r"(b0), "r"(b1))

__device__ __forceinline__ unsigned int pack_bf16x2(float hi, float lo) {
    unsigned int r;
    asm("cvt.rn.bf16x2.f32 %0, %1, %2;" : "=r"(r) : "f"(hi), "f"(lo));
    return r;
}

__device__ __forceinline__ void sts64(unsigned int addr, unsigned int p0, unsigned int p1) {
    asm volatile("st.shared.v2.b32 [%0], {%1, %2};" :: "r"(addr), "r"(p0), "r"(p1));
}

__global__ void __launch_bounds__(NTHR, 2)
gram_kernel(const float* __restrict__ T0, const float* __restrict__ R0, int M0, int nb0,
            const float* __restrict__ T1, const float* __restrict__ R1, int M1, int nb1,
            const float* __restrict__ T2, const float* __restrict__ R2, int M2, int nb2)
{
    __shared__ __align__(16) char smem_raw[2 * BUFB];
    const uint32_t sbase = (uint32_t)__cvta_generic_to_shared(smem_raw);

    const int tid  = threadIdx.x;
    const int wid  = tid >> 5;
    const int lane = tid & 31;

    // --- pick pair ---
    const float *T, *R; int M, lb, nb;
    int b = blockIdx.x;
    if (b < nb0)            { T = T0; R = R0; M = M0; lb = b;             nb = nb0; }
    else if (b < nb0 + nb1) { T = T1; R = R1; M = M1; lb = b - nb0;       nb = nb1; }
    else                    { T = T2; R = R2; M = M2; lb = b - nb0 - nb1; nb = nb2; }

    // --- loader mapping: warp w covers rows {r0, r0+1, r0+4, r0+5} so the
    //     swizzled STS.64s hit both 64B halves -> 2-phase (conflict-free). ---
    const int row = ((wid >> 1) << 3) + ((wid & 1) << 1)
                  + ((lane >> 3) & 1) + ((lane >> 4) << 2);
    const int c4  = lane & 7;
    const float* rbase = (row < BROWS) ? (T + (size_t)row * (size_t)M)
                                       : (R + (size_t)(row - BROWS) * (size_t)M);
    const float4* g4 = (const float4*)rbase + c4;

    uint32_t stsA[4];
#pragma unroll
    for (int t = 0; t < 4; t++) {
        int inb = c4 * 8 + 64 * (t & 1);
        int off = row * 128 + inb;
        stsA[t] = sbase + (t >> 1) * 4096 + (off ^ ((row & 7) << 4));
    }

    // --- ldmatrix addresses: warp wid owns k16-step wid (k in [16w,16w+16)) ---
    const int q  = wid >> 2;            // sub-tile (k 0-63 / 64-127)
    const int ko = (wid & 3) * 32;      // byte offset of k16 within 128B row
    const int kb = (lane & 16);         // klo / khi 8x8 matrices
    const int rw = lane & 15;
    int oA = rw * 128 + ko + kb;        oA = q * 4096 + (oA ^ ((rw & 7) << 4));
    int rB = rw + 16;
    int oB = rB * 128 + ko + kb;        oB = q * 4096 + (oB ^ ((rB & 7) << 4));
    const uint32_t lds00 = sbase + oA, lds01 = sbase + oB;        // buf0
    const uint32_t lds10 = lds00 + BUFB, lds11 = lds01 + BUFB;    // buf1

    float acc[8][4];
#pragma unroll
    for (int i = 0; i < 8; i++)
#pragma unroll
        for (int jj = 0; jj < 4; jj++) acc[i][jj] = 0.f;
    float rsum = 0.f;

    const int niter = M >> 7;                       // TKI = 128
    const int cnt = (niter - lb + nb - 1) / nb;

    float4 vA[4], vB[4];
#pragma unroll
    for (int t = 0; t < 4; t++)
        vA[t] = __ldg(g4 + (size_t)lb * 32 + t * 8);
    if (cnt > 1) {
#pragma unroll
        for (int t = 0; t < 4; t++)
            vB[t] = __ldg(g4 + (size_t)(lb + nb) * 32 + t * 8);
    }

    auto stage = [&](float4* v, uint32_t bofs) {
#pragma unroll
        for (int t = 0; t < 4; t++) {
            float e0 = __expf(v[t].x), e1 = __expf(v[t].y);
            float e2 = __expf(v[t].z), e3 = __expf(v[t].w);
            rsum += (e0 + e1) + (e2 + e3);
            sts64(stsA[t] + bofs, pack_bf16x2(e1, e0), pack_bf16x2(e3, e2));
        }
    };
    auto mma_phase = [&](uint32_t a0addr, uint32_t a1addr) {
        uint32_t L0[4], L1[4];
        LDSM_X4(L0[0], L0[1], L0[2], L0[3], a0addr);   // rows 0-15
        LDSM_X4(L1[0], L1[1], L1[2], L1[3], a1addr);   // rows 16-31
        MMA16816(acc[0], L0[0], L0[1], L0[2], L0[3], L0[0], L0[2]);  // m0-15 n0-7
        MMA16816(acc[1], L0[0], L0[1], L0[2], L0[3], L0[1], L0[3]);  // n8-15
        MMA16816(acc[2], L0[0], L0[1], L0[2], L0[3], L1[0], L1[2]);  // n16-23
        MMA16816(acc[3], L0[0], L0[1], L0[2], L0[3], L1[1], L1[3]);  // n24-31
        MMA16816(acc[4], L1[0], L1[1], L1[2], L1[3], L0[0], L0[2]);  // m16-31
        MMA16816(acc[5], L1[0], L1[1], L1[2], L1[3], L0[1], L0[3]);
        MMA16816(acc[6], L1[0], L1[1], L1[2], L1[3], L1[0], L1[2]);
        MMA16816(acc[7], L1[0], L1[1], L1[2], L1[3], L1[1], L1[3]);
    };

    int j = 0;
    while (true) {
        stage(vA, 0);
        {
            int pf = lb + (j + 2) * nb;
            if (pf < niter) {
#pragma unroll
                for (int t = 0; t < 4; t++)
                    vA[t] = __ldg(g4 + (size_t)pf * 32 + t * 8);
            }
        }
        __syncthreads();
        mma_phase(lds00, lds01);
        j++; if (j >= cnt) break;

        stage(vB, BUFB);
        {
            int pf = lb + (j + 2) * nb;
            if (pf < niter) {
#pragma unroll
                for (int t = 0; t < 4; t++)
                    vB[t] = __ldg(g4 + (size_t)pf * 32 + t * 8);
            }
        }
        __syncthreads();
        mma_phase(lds10, lds11);
        j++; if (j >= cnt) break;
    }

    // --- block-level combine (reuse staging smem), then plain-store slot ---
    __syncthreads();
    float* gc = (float*)smem_raw;       // [32][33]
    float* rs = gc + 32 * 33;           // [32]
    for (int i = tid; i < 32 * 33 + 32; i += NTHR) gc[i] = 0.f;
    __syncthreads();

    {
        const int fr = lane >> 2;
        const int fc = 2 * (lane & 3);
#pragma unroll
        for (int mi = 0; mi < 2; mi++)
#pragma unroll
            for (int nt = 0; nt < 4; nt++) {
                float* a = acc[mi * 4 + nt];
                int r = mi * 16 + fr;
                int c = nt * 8 + fc;
                atomicAdd(&gc[r * 33 + c],           a[0]);
                atomicAdd(&gc[r * 33 + c + 1],       a[1]);
                atomicAdd(&gc[(r + 8) * 33 + c],     a[2]);
                atomicAdd(&gc[(r + 8) * 33 + c + 1], a[3]);
            }
        float s = rsum;
        s += __shfl_xor_sync(0xffffffffu, s, 1);
        s += __shfl_xor_sync(0xffffffffu, s, 2);
        s += __shfl_xor_sync(0xffffffffu, s, 4);
        if ((lane & 7) == 0) atomicAdd(&rs[row], s);
    }
    __syncthreads();

    float* slot = g_bgram[blockIdx.x];
    for (int i = tid; i < 1024; i += NTHR)
        slot[i] = gc[(i >> 5) * 33 + (i & 31)];
    if (tid < 32) slot[1024 + tid] = rs[tid];
}

// ---------------------------------------------------------------------------
// Sinkhorn solver: 3 blocks (one per pair), 1024 threads = 4 softmins x 16x16.
// Cross-block partial reduction in FP32 (8 independent accumulators); fp64
// only for the final C-matrix build.
// ---------------------------------------------------------------------------
__global__ void __launch_bounds__(1024, 1)
solver_kernel(float* out, int nb0, int nb1, int nb2)
{
    const int p = blockIdx.x;
    __shared__ double sG[32][32];
    __shared__ double sS[32];
    __shared__ float Cxy[16][16], Cxx[16][16], Cyy[16][16];
    __shared__ float pot[2][4][16];
    __shared__ float fin[4][16];
    __shared__ float epss[60];

    const int tid = threadIdx.x;
    const int q = tid >> 8;
    const int i = (tid >> 4) & 15;
    const int j = tid & 15;

    const int off  = (p == 0) ? 0 : ((p == 1) ? nb0 : nb0 + nb1);
    const int cntb = (p == 0) ? nb0 : ((p == 1) ? nb1 : nb2);

    // --- reduce block partials in FP32: 8 independent accumulators ---
    {
        const bool hasS = (tid < 32);
        float a0 = 0.f, a1 = 0.f, a2 = 0.f, a3 = 0.f;
        float a4 = 0.f, a5 = 0.f, a6 = 0.f, a7 = 0.f;
        float s0 = 0.f, s1 = 0.f, s2 = 0.f, s3 = 0.f;
        float s4 = 0.f, s5 = 0.f, s6 = 0.f, s7 = 0.f;
        int b2 = 0;
        for (; b2 + 8 <= cntb; b2 += 8) {
            const float* r0 = g_bgram[off + b2];
            a0 += __ldg(r0 + tid);
            a1 += __ldg(r0 + 1056 + tid);
            a2 += __ldg(r0 + 2 * 1056 + tid);
            a3 += __ldg(r0 + 3 * 1056 + tid);
            a4 += __ldg(r0 + 4 * 1056 + tid);
            a5 += __ldg(r0 + 5 * 1056 + tid);
            a6 += __ldg(r0 + 6 * 1056 + tid);
            a7 += __ldg(r0 + 7 * 1056 + tid);
            if (hasS) {
                const float* rsrc = r0 + 1024 + tid;
                s0 += __ldg(rsrc);
                s1 += __ldg(rsrc + 1056);
                s2 += __ldg(rsrc + 2 * 1056);
                s3 += __ldg(rsrc + 3 * 1056);
                s4 += __ldg(rsrc + 4 * 1056);
                s5 += __ldg(rsrc + 5 * 1056);
                s6 += __ldg(rsrc + 6 * 1056);
                s7 += __ldg(rsrc + 7 * 1056);
            }
        }
        for (; b2 < cntb; b2++) {
            a0 += __ldg(&g_bgram[off + b2][tid]);
            if (hasS) s0 += __ldg(&g_bgram[off + b2][1024 + tid]);
        }
        sG[tid >> 5][tid & 31] =
            (double)(((a0 + a1) + (a2 + a3)) + ((a4 + a5) + (a6 + a7)));
        if (hasS)
            sS[tid] = (double)(((s0 + s1) + (s2 + s3)) + ((s4 + s5) + (s6 + s7)));
    }
    if (tid < 60) {
        // (0.95^2)^k, clamped at blur^2; fp32 exp2 (rel err ~1e-7, harmless)
        epss[tid] = fmaxf(exp2f((float)tid * -0.14800216f), 0.0025f);
    }
    if (tid < 64) pot[0][tid >> 4][tid & 15] = 0.f;
    __syncthreads();

    if (tid < 256) {
        int ii = tid >> 4, jj = tid & 15;
        double Si  = sS[ii],      Sj  = sS[jj];
        double Syi = sS[16 + ii], Syj = sS[16 + jj];
        double a2i = sG[ii][ii] / (Si * Si);
        double a2j = sG[jj][jj] / (Sj * Sj);
        double b2i = sG[16 + ii][16 + ii] / (Syi * Syi);
        double b2j = sG[16 + jj][16 + jj] / (Syj * Syj);
        double dxy = sG[ii][16 + jj] / (Si * Syj);
        int lo = min(ii, jj), hi = max(ii, jj);
        double dxx = sG[lo][hi]           / (Si * Sj);
        double dyy = sG[16 + lo][16 + hi] / (Syi * Syj);
        Cxy[ii][jj] = (float)(0.5 * (a2i + b2j) - dxy);
        Cxx[ii][jj] = (float)(0.5 * (a2i + a2j) - dxx);
        Cyy[ii][jj] = (float)(0.5 * (b2i + b2j) - dyy);
    }
    __syncthreads();

    int cur = 0;
    for (int s = 0; s < 60; s++) {
        float eps = epss[s];
        float inv_eps = 1.0f / eps;
        float h, Cv, old;
        if (q == 0)      { h = pot[cur][1][j]; Cv = Cxy[i][j]; old = pot[cur][0][i]; }
        else if (q == 1) { h = pot[cur][0][j]; Cv = Cxy[j][i]; old = pot[cur][1][i]; }
        else if (q == 2) { h = pot[cur][2][j]; Cv = Cxx[i][j]; old = pot[cur][2][i]; }
        else             { h = pot[cur][3][j]; Cv = Cyy[i][j]; old = pot[cur][3][i]; }
        float u = (h - Cv) * inv_eps;
        float t = u * fmaf(u, fmaf(u, 0.16666667f, 0.5f), 1.0f);   // expm1
        t += __shfl_xor_sync(0xffffffffu, t, 1);
        t += __shfl_xor_sync(0xffffffffu, t, 2);
        t += __shfl_xor_sync(0xffffffffu, t, 4);
        t += __shfl_xor_sync(0xffffffffu, t, 8);
        if (j == 0) {
            float m = t * 0.0625f;
            float l = m * fmaf(m, fmaf(m, 0.33333333f, -0.5f), 1.0f);  // log1p
            pot[cur ^ 1][q][i] = 0.5f * (old - eps * l);
        }
        __syncthreads();
        cur ^= 1;
    }

    {
        const float eps = 0.0025f;
        const float inv_eps = 1.0f / eps;
        float h, Cv;
        if (q == 0)      { h = pot[cur][1][j]; Cv = Cxy[i][j]; }
        else if (q == 1) { h = pot[cur][0][j]; Cv = Cxy[j][i]; }
        else if (q == 2) { h = pot[cur][2][j]; Cv = Cxx[i][j]; }
        else             { h = pot[cur][3][j]; Cv = Cyy[i][j]; }
        float u = (h - Cv) * inv_eps;
        float t = u * fmaf(u, fmaf(u, 0.16666667f, 0.5f), 1.0f);
        t += __shfl_xor_sync(0xffffffffu, t, 1);
        t += __shfl_xor_sync(0xffffffffu, t, 2);
        t += __shfl_xor_sync(0xffffffffu, t, 4);
        t += __shfl_xor_sync(0xffffffffu, t, 8);
        if (j == 0) {
            float m = t * 0.0625f;
            float l = m * fmaf(m, fmaf(m, 0.33333333f, -0.5f), 1.0f);
            fin[q][i] = -eps * l;
        }
        __syncthreads();
    }

    if (tid == 0) {
        double acc2 = 0.0;
        for (int ii = 0; ii < 16; ii++)
            acc2 += ((double)fin[0][ii] - (double)fin[2][ii])
                  + ((double)fin[1][ii] - (double)fin[3][ii]);
        g_partial[p] = acc2 / 48.0;          // mean over 16, /3 pairs
        __threadfence();
        unsigned int tk = atomicAdd(&g_ctr, 1);
        if (tk == 2) {
            out[0] = (float)(g_partial[0] + g_partial[1] + g_partial[2]);
            g_ctr = 0;                       // self-reset for graph replay
        }
    }
}

// ---------------------------------------------------------------------------
extern "C" void kernel_launch(void* const* d_in, const int* in_sizes, int n_in,
                              void* d_out, int out_size)
{
    (void)out_size;
    // Pair the 6 inputs by element count (divergence is symmetric in (x, y)).
    int idx[6] = {0, 1, 2, 3, 4, 5};
    int n = (n_in < 6) ? n_in : 6;
    for (int a = 0; a < n; a++)
        for (int b = a + 1; b < n; b++)
            if (in_sizes[idx[b]] > in_sizes[idx[a]]) {
                int tmp = idx[a]; idx[a] = idx[b]; idx[b] = tmp;
            }

    const float* T[3]; const float* R[3]; int M[3]; int nb[3];
    for (int p = 0; p < 3; p++) {
        T[p] = (const float*)d_in[idx[2 * p]];
        R[p] = (const float*)d_in[idx[2 * p + 1]];
        M[p] = in_sizes[idx[2 * p]] / BROWS;
        int iters = M[p] >> 7;                 // TKI = 128
        nb[p] = (iters + 48) / 49;             // ~49 iters/block, <=296 blocks total
        if (nb[p] < 1) nb[p] = 1;
        if (nb[p] > iters) nb[p] = iters;
    }
    // slot-array safety: total blocks must fit g_bgram (304 slots)
    int tot = nb[0] + nb[1] + nb[2];
    if (tot > 304) { nb[0] -= (tot - 304); if (nb[0] < 1) nb[0] = 1; tot = nb[0] + nb[1] + nb[2]; }

    gram_kernel<<<tot, NTHR>>>(
        T[0], R[0], M[0], nb[0],
        T[1], R[1], M[1], nb[1],
        T[2], R[2], M[2], nb[2]);
    solver_kernel<<<3, 1024>>>((float*)d_out, nb[0], nb[1], nb[2]);
}

// round 10
// speedup vs baseline: 2.4327x; 1.0641x over previous
#include <cuda_runtime.h>
#include <math.h>
#include <stdint.h>

// ---------------------------------------------------------------------------
// Revisit_RDLoss: debiased Sinkhorn divergence over softmax rows, 3 pairs.
// SINGLE fused kernel:
//   Gram phase (per block): Z = [exp(teacher); exp(rec)] (32 x M).
//     TKI=128 K/iter, 256 thr, 2 blocks/SM: fp32 load -> exp -> bf16 ->
//     SW128 smem, double-buffered; 8 warps x (2 ldmatrix.x4 + 8 HMMA)
//     exploiting Gram symmetry (A frags reused as B). fp32 block partials
//     plain-stored to a per-block slot. (Measured at the HBM roofline.)
//   Solver phase (last block of each pair, via per-pair atomic ticket):
//     reduce slots in fp32 (MLP), build C matrices in fp32 (reciprocals, no
//     fp64 anywhere -- C abs err ~1e-13 << eps; Cxx diag cancels exactly),
//     run the 60-step eps-scaled Sinkhorn with softmin =
//     -eps*log1p(mean_j expm1((h_j-C_ij)/eps)) via cubic Taylor (|u|<=1e-2).
//     Last pair writes d_out via a global ticket. All counters self-reset.
// ---------------------------------------------------------------------------

#define BROWS 16
#define NTHR  256            // 8 warps
#define BUFB  8192           // bytes per smem buffer (2 sub-tiles x 4096)

__device__ float        g_bgram[304][1056];   // per-block partials: 1024 gram + 32 sums
__device__ float        g_partial[3];
__device__ unsigned int g_pctr[3];            // per-pair completion tickets
__device__ unsigned int g_ctr;                // global ticket; all self-reset

// ---- PTX helpers ------------------------------------------------------------
#define LDSM_X4(r0, r1, r2, r3, a)                                          \
    asm volatile("ldmatrix.sync.aligned.x4.m8n8.shared.b16 {%0,%1,%2,%3}, [%4];" \
                 : "=r"(r0), "=r"(r1), "=r"(r2), "=r"(r3) : "r"(a))

#define MMA16816(c, a0, a1, a2, a3, b0, b1)                                 \
    asm volatile("mma.sync.aligned.m16n8k16.row.col.f32.bf16.bf16.f32 "     \
                 "{%0,%1,%2,%3}, {%4,%5,%6,%7}, {%8,%9}, {%0,%1,%2,%3};"    \
                 : "+f"((c)[0]), "+f"((c)[1]), "+f"((c)[2]), "+f"((c)[3])   \
                 : "r"(a0), "r"(a1), "r"(a2), "r"(a3), "r"(b0), "r"(b1))

__device__ __forceinline__ unsigned int pack_bf16x2(float hi, float lo) {
    unsigned int r;
    asm("cvt.rn.bf16x2.f32 %0, %1, %2;" : "=r"(r) : "f"(hi), "f"(lo));
    return r;
}

__device__ __forceinline__ void sts64(unsigned int addr, unsigned int p0, unsigned int p1) {
    asm volatile("st.shared.v2.b32 [%0], {%1, %2};" :: "r"(addr), "r"(p0), "r"(p1));
}

// solver smem overlay (fits in the 16 KB staging buffers)
struct SolverSmem {
    float sG[1024];           // reduced gram (row-major 32x32)
    float sS[32];             // row sums
    float sIS[32];            // 1/S
    float sA2[32];            // ||row||^2 normalized
    float C[4][16][17];       // 0:Cxy 1:CxyT 2:Cxx 3:Cyy (padded rows)
    float pot[2][4][16];
    float fin[4][16];
    float epss[60];
    unsigned int last_flag;
};

__global__ void __launch_bounds__(NTHR, 2)
fused_kernel(const float* __restrict__ T0, const float* __restrict__ R0, int M0, int nb0,
             const float* __restrict__ T1, const float* __restrict__ R1, int M1, int nb1,
             const float* __restrict__ T2, const float* __restrict__ R2, int M2, int nb2,
             float* __restrict__ out)
{
    __shared__ __align__(16) char smem_raw[2 * BUFB];
    const uint32_t sbase = (uint32_t)__cvta_generic_to_shared(smem_raw);

    const int tid  = threadIdx.x;
    const int wid  = tid >> 5;
    const int lane = tid & 31;

    // --- pick pair ---
    const float *T, *R; int M, lb, nb, pair, poff;
    int b = blockIdx.x;
    if (b < nb0)            { T = T0; R = R0; M = M0; lb = b;             nb = nb0; pair = 0; poff = 0; }
    else if (b < nb0 + nb1) { T = T1; R = R1; M = M1; lb = b - nb0;       nb = nb1; pair = 1; poff = nb0; }
    else                    { T = T2; R = R2; M = M2; lb = b - nb0 - nb1; nb = nb2; pair = 2; poff = nb0 + nb1; }
    const int cntb = nb;

    // =========================== GRAM PHASE =================================
    // loader mapping: warp w covers rows {r0, r0+1, r0+4, r0+5} (2-phase STS)
    const int row = ((wid >> 1) << 3) + ((wid & 1) << 1)
                  + ((lane >> 3) & 1) + ((lane >> 4) << 2);
    const int c4  = lane & 7;
    const float* rbase = (row < BROWS) ? (T + (size_t)row * (size_t)M)
                                       : (R + (size_t)(row - BROWS) * (size_t)M);
    const float4* g4 = (const float4*)rbase + c4;

    uint32_t stsA[4];
#pragma unroll
    for (int t = 0; t < 4; t++) {
        int inb = c4 * 8 + 64 * (t & 1);
        int off = row * 128 + inb;
        stsA[t] = sbase + (t >> 1) * 4096 + (off ^ ((row & 7) << 4));
    }

    // ldmatrix addresses: warp wid owns k16-step wid
    const int q2 = wid >> 2;
    const int ko = (wid & 3) * 32;
    const int kb = (lane & 16);
    const int rw = lane & 15;
    int oA = rw * 128 + ko + kb;        oA = q2 * 4096 + (oA ^ ((rw & 7) << 4));
    int rB = rw + 16;
    int oB = rB * 128 + ko + kb;        oB = q2 * 4096 + (oB ^ ((rB & 7) << 4));
    const uint32_t lds00 = sbase + oA, lds01 = sbase + oB;
    const uint32_t lds10 = lds00 + BUFB, lds11 = lds01 + BUFB;

    float acc[8][4];
#pragma unroll
    for (int i = 0; i < 8; i++)
#pragma unroll
        for (int jj = 0; jj < 4; jj++) acc[i][jj] = 0.f;
    float rsum = 0.f;

    const int niter = M >> 7;                       // TKI = 128
    const int cnt = (niter - lb + nb - 1) / nb;

    float4 vA[4], vB[4];
#pragma unroll
    for (int t = 0; t < 4; t++)
        vA[t] = __ldg(g4 + (size_t)lb * 32 + t * 8);
    if (cnt > 1) {
#pragma unroll
        for (int t = 0; t < 4; t++)
            vB[t] = __ldg(g4 + (size_t)(lb + nb) * 32 + t * 8);
    }

    auto stage = [&](float4* v, uint32_t bofs) {
#pragma unroll
        for (int t = 0; t < 4; t++) {
            float e0 = __expf(v[t].x), e1 = __expf(v[t].y);
            float e2 = __expf(v[t].z), e3 = __expf(v[t].w);
            rsum += (e0 + e1) + (e2 + e3);
            sts64(stsA[t] + bofs, pack_bf16x2(e1, e0), pack_bf16x2(e3, e2));
        }
    };
    auto mma_phase = [&](uint32_t a0addr, uint32_t a1addr) {
        uint32_t L0[4], L1[4];
        LDSM_X4(L0[0], L0[1], L0[2], L0[3], a0addr);
        LDSM_X4(L1[0], L1[1], L1[2], L1[3], a1addr);
        MMA16816(acc[0], L0[0], L0[1], L0[2], L0[3], L0[0], L0[2]);
        MMA16816(acc[1], L0[0], L0[1], L0[2], L0[3], L0[1], L0[3]);
        MMA16816(acc[2], L0[0], L0[1], L0[2], L0[3], L1[0], L1[2]);
        MMA16816(acc[3], L0[0], L0[1], L0[2], L0[3], L1[1], L1[3]);
        MMA16816(acc[4], L1[0], L1[1], L1[2], L1[3], L0[0], L0[2]);
        MMA16816(acc[5], L1[0], L1[1], L1[2], L1[3], L0[1], L0[3]);
        MMA16816(acc[6], L1[0], L1[1], L1[2], L1[3], L1[0], L1[2]);
        MMA16816(acc[7], L1[0], L1[1], L1[2], L1[3], L1[1], L1[3]);
    };

    int j = 0;
    while (true) {
        stage(vA, 0);
        {
            int pf = lb + (j + 2) * nb;
            if (pf < niter) {
#pragma unroll
                for (int t = 0; t < 4; t++)
                    vA[t] = __ldg(g4 + (size_t)pf * 32 + t * 8);
            }
        }
        __syncthreads();
        mma_phase(lds00, lds01);
        j++; if (j >= cnt) break;

        stage(vB, BUFB);
        {
            int pf = lb + (j + 2) * nb;
            if (pf < niter) {
#pragma unroll
                for (int t = 0; t < 4; t++)
                    vB[t] = __ldg(g4 + (size_t)pf * 32 + t * 8);
            }
        }
        __syncthreads();
        mma_phase(lds10, lds11);
        j++; if (j >= cnt) break;
    }

    // --- block combine (reuse staging smem), plain-store slot ---
    __syncthreads();
    {
        float* gc = (float*)smem_raw;       // [32][33]
        float* rs = gc + 32 * 33;           // [32]
        for (int i = tid; i < 32 * 33 + 32; i += NTHR) gc[i] = 0.f;
        __syncthreads();

        const int fr = lane >> 2;
        const int fc = 2 * (lane & 3);
#pragma unroll
        for (int mi = 0; mi < 2; mi++)
#pragma unroll
            for (int nt = 0; nt < 4; nt++) {
                float* a = acc[mi * 4 + nt];
                int r = mi * 16 + fr;
                int c = nt * 8 + fc;
                atomicAdd(&gc[r * 33 + c],           a[0]);
                atomicAdd(&gc[r * 33 + c + 1],       a[1]);
                atomicAdd(&gc[(r + 8) * 33 + c],     a[2]);
                atomicAdd(&gc[(r + 8) * 33 + c + 1], a[3]);
            }
        float s = rsum;
        s += __shfl_xor_sync(0xffffffffu, s, 1);
        s += __shfl_xor_sync(0xffffffffu, s, 2);
        s += __shfl_xor_sync(0xffffffffu, s, 4);
        if ((lane & 7) == 0) atomicAdd(&rs[row], s);
        __syncthreads();

        float* slot = g_bgram[blockIdx.x];
        for (int i = tid; i < 1024; i += NTHR)
            slot[i] = gc[(i >> 5) * 33 + (i & 31)];
        if (tid < 32) slot[1024 + tid] = rs[tid];
    }

    // --- per-pair ticket: only the last block continues ---
    SolverSmem* ss = (SolverSmem*)smem_raw;
    __threadfence();
    __syncthreads();                 // slot stores done by all threads
    if (tid == 0) {
        unsigned int tk = atomicAdd(&g_pctr[pair], 1);
        ss->last_flag = (tk == (unsigned int)(cntb - 1));
        if (ss->last_flag) g_pctr[pair] = 0;     // self-reset
    }
    __syncthreads();
    if (!ss->last_flag) return;
    __threadfence();                 // acquire: other blocks' slots visible

    // =========================== SOLVER PHASE ================================
    // reduce slots in fp32: thread -> 4 gram entries (+1 sum for tid<32)
    {
        float a0 = 0.f, a1 = 0.f, a2 = 0.f, a3 = 0.f, s0 = 0.f;
        const bool hasS = (tid < 32);
        for (int b2 = 0; b2 < cntb; b2++) {
            const float* r0 = g_bgram[poff + b2];
            a0 += __ldg(r0 + tid);
            a1 += __ldg(r0 + 256 + tid);
            a2 += __ldg(r0 + 512 + tid);
            a3 += __ldg(r0 + 768 + tid);
            if (hasS) s0 += __ldg(r0 + 1024 + tid);
        }
        ss->sG[tid]       = a0;
        ss->sG[256 + tid] = a1;
        ss->sG[512 + tid] = a2;
        ss->sG[768 + tid] = a3;
        if (hasS) ss->sS[tid] = s0;
    }
    if (tid < 60)
        ss->epss[tid] = fmaxf(exp2f((float)tid * -0.14800216f), 0.0025f);
    if (tid < 64) ss->pot[0][tid >> 4][tid & 15] = 0.f;
    __syncthreads();

    if (tid < 32) {
        float inv = 1.0f / ss->sS[tid];
        ss->sIS[tid] = inv;
        ss->sA2[tid] = (ss->sG[tid * 32 + tid] * inv) * inv;
    }
    __syncthreads();

    // build C matrices (fp32): entry (ii, jj) per thread
    {
        int ii = tid >> 4, jj = tid & 15;
        float ISi  = ss->sIS[ii],      ISj  = ss->sIS[jj];
        float ISyi = ss->sIS[16 + ii], ISyj = ss->sIS[16 + jj];
        float a2i = ss->sA2[ii], a2j = ss->sA2[jj];
        float b2i = ss->sA2[16 + ii], b2j = ss->sA2[16 + jj];
        int lo = min(ii, jj), hi = max(ii, jj);
        float cxy = fmaf(-ss->sG[ii * 32 + 16 + jj] * ISi, ISyj, 0.5f * (a2i + b2j));
        float cxx = 0.5f * (a2i + a2j) - (ss->sG[lo * 32 + hi] * ISi) * ISj;
        float cyy = 0.5f * (b2i + b2j) - (ss->sG[(16 + lo) * 32 + 16 + hi] * ISyi) * ISyj;
        if (ii == jj) { cxx = 0.f; cyy = 0.f; }     // exact diagonal
        ss->C[0][ii][jj] = cxy;
        ss->C[1][jj][ii] = cxy;                     // transposed copy
        ss->C[2][ii][jj] = cxx;
        ss->C[3][ii][jj] = cyy;
    }
    __syncthreads();

    // 60-step scan: q = tid>>6 (softmin id), i = (tid>>2)&15, jg = tid&3
    {
        const int q  = tid >> 6;
        const int i  = (tid >> 2) & 15;
        const int jg = tid & 3;
        const int hq = (q == 0) ? 1 : ((q == 1) ? 0 : q);
        const float* Crow = ss->C[q][i];

        int cur = 0;
        for (int s = 0; s < 60; s++) {
            float eps = ss->epss[s];
            float inv_eps = 1.0f / eps;
            const float* hp = ss->pot[cur][hq];
            float old = ss->pot[cur][q][i];
            float t = 0.f;
#pragma unroll
            for (int it = 0; it < 4; it++) {
                int jj = jg * 4 + it;
                float u = (hp[jj] - Crow[jj]) * inv_eps;
                t += u * fmaf(u, fmaf(u, 0.16666667f, 0.5f), 1.0f);   // expm1
            }
            t += __shfl_xor_sync(0xffffffffu, t, 1);
            t += __shfl_xor_sync(0xffffffffu, t, 2);
            if (jg == 0) {
                float m = t * 0.0625f;
                float l = m * fmaf(m, fmaf(m, 0.33333333f, -0.5f), 1.0f);  // log1p
                ss->pot[cur ^ 1][q][i] = 0.5f * (old - eps * l);
            }
            __syncthreads();
            cur ^= 1;
        }

        // final extrapolation at eps = 0.0025
        {
            const float eps = 0.0025f;
            const float inv_eps = 1.0f / eps;
            const float* hp = ss->pot[cur][hq];
            float t = 0.f;
#pragma unroll
            for (int it = 0; it < 4; it++) {
                int jj = jg * 4 + it;
                float u = (hp[jj] - Crow[jj]) * inv_eps;
                t += u * fmaf(u, fmaf(u, 0.16666667f, 0.5f), 1.0f);
            }
            t += __shfl_xor_sync(0xffffffffu, t, 1);
            t += __shfl_xor_sync(0xffffffffu, t, 2);
            if (jg == 0) {
                float m = t * 0.0625f;
                float l = m * fmaf(m, fmaf(m, 0.33333333f, -0.5f), 1.0f);
                ss->fin[q][i] = -eps * l;
            }
            __syncthreads();
        }
    }

    if (tid == 0) {
        float acc2 = 0.f;
#pragma unroll
        for (int ii = 0; ii < 16; ii++)
            acc2 += (ss->fin[0][ii] - ss->fin[2][ii])
                  + (ss->fin[1][ii] - ss->fin[3][ii]);
        g_partial[pair] = acc2 / 48.0f;      // mean over 16, /3 pairs
        __threadfence();
        unsigned int tk = atomicAdd(&g_ctr, 1);
        if (tk == 2) {
            out[0] = g_partial[0] + g_partial[1] + g_partial[2];
            g_ctr = 0;                       // self-reset for graph replay
        }
    }
}

// ---------------------------------------------------------------------------
extern "C" void kernel_launch(void* const* d_in, const int* in_sizes, int n_in,
                              void* d_out, int out_size)
{
    (void)out_size;
    // Pair the 6 inputs by element count (divergence is symmetric in (x, y)).
    int idx[6] = {0, 1, 2, 3, 4, 5};
    int n = (n_in < 6) ? n_in : 6;
    for (int a = 0; a < n; a++)
        for (int b = a + 1; b < n; b++)
            if (in_sizes[idx[b]] > in_sizes[idx[a]]) {
                int tmp = idx[a]; idx[a] = idx[b]; idx[b] = tmp;
            }

    const float* T[3]; const float* R[3]; int M[3]; int nb[3];
    for (int p = 0; p < 3; p++) {
        T[p] = (const float*)d_in[idx[2 * p]];
        R[p] = (const float*)d_in[idx[2 * p + 1]];
        M[p] = in_sizes[idx[2 * p]] / BROWS;
        int iters = M[p] >> 7;                 // TKI = 128
        nb[p] = (iters + 48) / 49;             // ~49 iters/block, <=296 blocks total
        if (nb[p] < 1) nb[p] = 1;
        if (nb[p] > iters) nb[p] = iters;
    }
    // slot-array safety: total blocks must fit g_bgram (304 slots)
    int tot = nb[0] + nb[1] + nb[2];
    if (tot > 304) { nb[0] -= (tot - 304); if (nb[0] < 1) nb[0] = 1; tot = nb[0] + nb[1] + nb[2]; }

    fused_kernel<<<tot, NTHR>>>(
        T[0], R[0], M[0], nb[0],
        T[1], R[1], M[1], nb[1],
        T[2], R[2], M[2], nb[2],
        (float*)d_out);
}

// round 11
// speedup vs baseline: 2.5243x; 1.0377x over previous
#include <cuda_runtime.h>
#include <math.h>
#include <stdint.h>

// ---------------------------------------------------------------------------
// Revisit_RDLoss: debiased Sinkhorn divergence over softmax rows, 3 pairs.
// SINGLE fused kernel:
//   Gram phase: Z = [exp(teacher); exp(rec)] (32 x M), G = Z Z^T + row sums.
//     cp.async (LDGSTS) ring, depth 3 x 16KB raw fp32 per block (each thread
//     copies and reads ONLY its own 16 floats -> per-thread wait_group, no
//     producer barriers; ~64KB loads in flight per SM, vs the register
//     double-buffer's ~18KB that left DRAM at 38.8%).  Per iter: LDS raw ->
//     issue next cp.async -> exp -> bf16 pack -> SW128 smem -> one
//     __syncthreads -> 2 ldmatrix.x4 + 8 HMMA per warp (Gram symmetry: A
//     frags reused as B). fp32 block partials plain-stored per-block.
//   Solver phase (last block per pair via atomic ticket): fp32 reduction,
//     fp32 C-build (no fp64 anywhere), 60-step eps-scaled Sinkhorn with
//     softmin = -eps*log1p(mean_j expm1(u)) via cubic Taylor (|u|<=1e-2).
//     Last pair writes d_out via a global ticket. Counters self-reset.
// ---------------------------------------------------------------------------

#define BROWS 16
#define NTHR  256                 // 8 warps
#define RAWP  544                 // raw row pitch bytes (136 floats; 544%128=32 -> conflict-free)
#define RAWS  (32 * RAWP)         // 17408 B per raw stage
#define BF16OFF (3 * RAWS)        // 52224: two 8KB bf16 buffers follow
#define SMEMB (BF16OFF + 2 * 8192)  // 68608 B dynamic smem per block

__device__ float        g_bgram[304][1056];   // per-block partials: 1024 gram + 32 sums
__device__ float        g_partial[3];
__device__ unsigned int g_pctr[3];            // per-pair completion tickets
__device__ unsigned int g_ctr;                // global ticket; all self-reset

// ---- PTX helpers ------------------------------------------------------------
#define LDSM_X4(r0, r1, r2, r3, a)                                          \
    asm volatile("ldmatrix.sync.aligned.x4.m8n8.shared.b16 {%0,%1,%2,%3}, [%4];" \
                 : "=r"(r0), "=r"(r1), "=r"(r2), "=r"(r3) : "r"(a))

#define MMA16816(c, a0, a1, a2, a3, b0, b1)                                 \
    asm volatile("mma.sync.aligned.m16n8k16.row.col.f32.bf16.bf16.f32 "     \
                 "{%0,%1,%2,%3}, {%4,%5,%6,%7}, {%8,%9}, {%0,%1,%2,%3};"    \
                 : "+f"((c)[0]), "+f"((c)[1]), "+f"((c)[2]), "+f"((c)[3])   \
                 : "r"(a0), "r"(a1), "r"(a2), "r"(a3), "r"(b0), "r"(b1))

#define CP_ASYNC16(dst, src)                                                \
    asm volatile("cp.async.cg.shared.global [%0], [%1], 16;" :: "r"(dst), "l"(src))
#define CP_COMMIT()  asm volatile("cp.async.commit_group;" ::: "memory")
#define CP_WAIT2()   asm volatile("cp.async.wait_group 2;" ::: "memory")

__device__ __forceinline__ unsigned int pack_bf16x2(float hi, float lo) {
    unsigned int r;
    asm("cvt.rn.bf16x2.f32 %0, %1, %2;" : "=r"(r) : "f"(hi), "f"(lo));
    return r;
}

__device__ __forceinline__ void sts64(unsigned int addr, unsigned int p0, unsigned int p1) {
    asm volatile("st.shared.v2.b32 [%0], {%1, %2};" :: "r"(addr), "r"(p0), "r"(p1));
}

// solver smem overlay (lives in the dynamic smem after gram is done)
struct SolverSmem {
    float sG[1024];           // reduced gram (row-major 32x32)
    float sS[32];             // row sums
    float sIS[32];            // 1/S
    float sA2[32];            // ||row||^2 normalized
    float C[4][16][17];       // 0:Cxy 1:CxyT 2:Cxx 3:Cyy (padded rows)
    float pot[2][4][16];
    float fin[4][16];
    float epss[60];
    unsigned int last_flag;
};

__global__ void __launch_bounds__(NTHR, 2)
fused_kernel(const float* __restrict__ T0, const float* __restrict__ R0, int M0, int nb0,
             const float* __restrict__ T1, const float* __restrict__ R1, int M1, int nb1,
             const float* __restrict__ T2, const float* __restrict__ R2, int M2, int nb2,
             float* __restrict__ out)
{
    extern __shared__ __align__(16) char smem_raw[];
    const uint32_t sbase = (uint32_t)__cvta_generic_to_shared(smem_raw);

    const int tid  = threadIdx.x;
    const int wid  = tid >> 5;
    const int lane = tid & 31;

    // --- pick pair ---
    const float *T, *R; int M, lb, nb, pair, poff;
    int b = blockIdx.x;
    if (b < nb0)            { T = T0; R = R0; M = M0; lb = b;             nb = nb0; pair = 0; poff = 0; }
    else if (b < nb0 + nb1) { T = T1; R = R1; M = M1; lb = b - nb0;       nb = nb1; pair = 1; poff = nb0; }
    else                    { T = T2; R = R2; M = M2; lb = b - nb0 - nb1; nb = nb2; pair = 2; poff = nb0 + nb1; }
    const int cntb = nb;

    // =========================== GRAM PHASE =================================
    // row/col mapping (same thread copies, reads, exps its own 16 floats):
    // warp w covers rows {r0, r0+1, r0+4, r0+5} (keeps bf16 STS 2-phase).
    const int row = ((wid >> 1) << 3) + ((wid & 1) << 1)
                  + ((lane >> 3) & 1) + ((lane >> 4) << 2);
    const int c4  = lane & 7;
    const float* rbase = (row < BROWS) ? (T + (size_t)row * (size_t)M)
                                       : (R + (size_t)(row - BROWS) * (size_t)M);
    const float4* g4 = (const float4*)rbase + c4;

    // raw-stage addresses: float4 t at row*RAWP + (c4 + 8t)*16
    const uint32_t rawoff = (uint32_t)(row * RAWP + c4 * 16);

    // bf16 STS addresses (SW128-swizzled, 2 sub-tiles of 32 x 128B)
    uint32_t stsA[4];
#pragma unroll
    for (int t = 0; t < 4; t++) {
        int inb = c4 * 8 + 64 * (t & 1);
        int off = row * 128 + inb;
        stsA[t] = sbase + BF16OFF + (t >> 1) * 4096 + (off ^ ((row & 7) << 4));
    }

    // ldmatrix addresses: warp wid owns k16-step wid
    const int q2 = wid >> 2;
    const int ko = (wid & 3) * 32;
    const int kb = (lane & 16);
    const int rw = lane & 15;
    int oA = rw * 128 + ko + kb;        oA = q2 * 4096 + (oA ^ ((rw & 7) << 4));
    int rB = rw + 16;
    int oB = rB * 128 + ko + kb;        oB = q2 * 4096 + (oB ^ ((rB & 7) << 4));
    const uint32_t lds00 = sbase + BF16OFF + oA, lds01 = sbase + BF16OFF + oB;
    const uint32_t lds10 = lds00 + 8192,         lds11 = lds01 + 8192;

    float acc[8][4];
#pragma unroll
    for (int i = 0; i < 8; i++)
#pragma unroll
        for (int jj = 0; jj < 4; jj++) acc[i][jj] = 0.f;
    float rsum = 0.f;

    const int niter = M >> 7;                       // TKI = 128
    const int cnt = (niter - lb + nb - 1) / nb;

    // issue stage s (chunk lb + s*nb) into ring slot; always commit a group
    auto issue = [&](int s2, uint32_t slotoff) {
        int chunk = lb + s2 * nb;
        if (chunk < niter) {
            uint32_t dst = sbase + slotoff + rawoff;
            const float4* src = g4 + (size_t)chunk * 32;
#pragma unroll
            for (int t = 0; t < 4; t++)
                CP_ASYNC16(dst + 128u * t, src + 8 * t);
        }
        CP_COMMIT();
    };

    auto mma_phase = [&](uint32_t a0addr, uint32_t a1addr) {
        uint32_t L0[4], L1[4];
        LDSM_X4(L0[0], L0[1], L0[2], L0[3], a0addr);
        LDSM_X4(L1[0], L1[1], L1[2], L1[3], a1addr);
        MMA16816(acc[0], L0[0], L0[1], L0[2], L0[3], L0[0], L0[2]);
        MMA16816(acc[1], L0[0], L0[1], L0[2], L0[3], L0[1], L0[3]);
        MMA16816(acc[2], L0[0], L0[1], L0[2], L0[3], L1[0], L1[2]);
        MMA16816(acc[3], L0[0], L0[1], L0[2], L0[3], L1[1], L1[3]);
        MMA16816(acc[4], L1[0], L1[1], L1[2], L1[3], L0[0], L0[2]);
        MMA16816(acc[5], L1[0], L1[1], L1[2], L1[3], L0[1], L0[3]);
        MMA16816(acc[6], L1[0], L1[1], L1[2], L1[3], L1[0], L1[2]);
        MMA16816(acc[7], L1[0], L1[1], L1[2], L1[3], L1[1], L1[3]);
    };

    // prologue: fill the 3-deep ring
    issue(0, 0);
    issue(1, RAWS);
    issue(2, 2 * RAWS);

    uint32_t cslot = 0;                 // byte offset of current raw slot
    for (int s = 0; s < cnt; s++) {
        CP_WAIT2();                     // own stage s landed (2 newest pending)

        // read own raw floats, then immediately refill this slot (stage s+3)
        float4 v[4];
        {
            const float4* praw = (const float4*)(smem_raw + cslot + rawoff);
#pragma unroll
            for (int t = 0; t < 4; t++) v[t] = praw[t * 8];
        }
        issue(s + 3, cslot);

        // exp -> bf16 -> swizzled smem
        uint32_t bofs = (s & 1) ? 8192u : 0u;
#pragma unroll
        for (int t = 0; t < 4; t++) {
            float e0 = __expf(v[t].x), e1 = __expf(v[t].y);
            float e2 = __expf(v[t].z), e3 = __expf(v[t].w);
            rsum += (e0 + e1) + (e2 + e3);
            sts64(stsA[t] + bofs, pack_bf16x2(e1, e0), pack_bf16x2(e3, e2));
        }
        __syncthreads();

        if (s & 1) mma_phase(lds10, lds11);
        else       mma_phase(lds00, lds01);

        cslot += RAWS; if (cslot == 3 * RAWS) cslot = 0;
    }

    // --- block combine (reuse bf16 smem area), plain-store slot ---
    __syncthreads();
    {
        float* gc = (float*)(smem_raw + BF16OFF);   // [32][33]
        float* rs = gc + 32 * 33;                   // [32]
        for (int i = tid; i < 32 * 33 + 32; i += NTHR) gc[i] = 0.f;
        __syncthreads();

        const int fr = lane >> 2;
        const int fc = 2 * (lane & 3);
#pragma unroll
        for (int mi = 0; mi < 2; mi++)
#pragma unroll
            for (int nt = 0; nt < 4; nt++) {
                float* a = acc[mi * 4 + nt];
                int r = mi * 16 + fr;
                int c = nt * 8 + fc;
                atomicAdd(&gc[r * 33 + c],           a[0]);
                atomicAdd(&gc[r * 33 + c + 1],       a[1]);
                atomicAdd(&gc[(r + 8) * 33 + c],     a[2]);
                atomicAdd(&gc[(r + 8) * 33 + c + 1], a[3]);
            }
        float s = rsum;
        s += __shfl_xor_sync(0xffffffffu, s, 1);
        s += __shfl_xor_sync(0xffffffffu, s, 2);
        s += __shfl_xor_sync(0xffffffffu, s, 4);
        if ((lane & 7) == 0) atomicAdd(&rs[row], s);
        __syncthreads();

        float* slot = g_bgram[blockIdx.x];
        for (int i = tid; i < 1024; i += NTHR)
            slot[i] = gc[(i >> 5) * 33 + (i & 31)];
        if (tid < 32) slot[1024 + tid] = rs[tid];
    }

    // --- per-pair ticket: only the last block continues ---
    SolverSmem* ss = (SolverSmem*)smem_raw;
    __threadfence();
    __syncthreads();
    if (tid == 0) {
        unsigned int tk = atomicAdd(&g_pctr[pair], 1);
        ss->last_flag = (tk == (unsigned int)(cntb - 1));
        if (ss->last_flag) g_pctr[pair] = 0;     // self-reset
    }
    __syncthreads();
    if (!ss->last_flag) return;
    __threadfence();                 // acquire: other blocks' slots visible

    // =========================== SOLVER PHASE ================================
    {
        float a0 = 0.f, a1 = 0.f, a2 = 0.f, a3 = 0.f, s0 = 0.f;
        const bool hasS = (tid < 32);
        for (int b2 = 0; b2 < cntb; b2++) {
            const float* r0 = g_bgram[poff + b2];
            a0 += __ldg(r0 + tid);
            a1 += __ldg(r0 + 256 + tid);
            a2 += __ldg(r0 + 512 + tid);
            a3 += __ldg(r0 + 768 + tid);
            if (hasS) s0 += __ldg(r0 + 1024 + tid);
        }
        ss->sG[tid]       = a0;
        ss->sG[256 + tid] = a1;
        ss->sG[512 + tid] = a2;
        ss->sG[768 + tid] = a3;
        if (hasS) ss->sS[tid] = s0;
    }
    if (tid < 60)
        ss->epss[tid] = fmaxf(exp2f((float)tid * -0.14800216f), 0.0025f);
    if (tid < 64) ss->pot[0][tid >> 4][tid & 15] = 0.f;
    __syncthreads();

    if (tid < 32) {
        float inv = 1.0f / ss->sS[tid];
        ss->sIS[tid] = inv;
        ss->sA2[tid] = (ss->sG[tid * 32 + tid] * inv) * inv;
    }
    __syncthreads();

    {
        int ii = tid >> 4, jj = tid & 15;
        float ISi  = ss->sIS[ii],      ISj  = ss->sIS[jj];
        float ISyi = ss->sIS[16 + ii], ISyj = ss->sIS[16 + jj];
        float a2i = ss->sA2[ii], a2j = ss->sA2[jj];
        float b2i = ss->sA2[16 + ii], b2j = ss->sA2[16 + jj];
        int lo = min(ii, jj), hi = max(ii, jj);
        float cxy = fmaf(-ss->sG[ii * 32 + 16 + jj] * ISi, ISyj, 0.5f * (a2i + b2j));
        float cxx = 0.5f * (a2i + a2j) - (ss->sG[lo * 32 + hi] * ISi) * ISj;
        float cyy = 0.5f * (b2i + b2j) - (ss->sG[(16 + lo) * 32 + 16 + hi] * ISyi) * ISyj;
        if (ii == jj) { cxx = 0.f; cyy = 0.f; }     // exact diagonal
        ss->C[0][ii][jj] = cxy;
        ss->C[1][jj][ii] = cxy;                     // transposed copy
        ss->C[2][ii][jj] = cxx;
        ss->C[3][ii][jj] = cyy;
    }
    __syncthreads();

    {
        const int q  = tid >> 6;
        const int i  = (tid >> 2) & 15;
        const int jg = tid & 3;
        const int hq = (q == 0) ? 1 : ((q == 1) ? 0 : q);
        const float* Crow = ss->C[q][i];

        int cur = 0;
        for (int s = 0; s < 60; s++) {
            float eps = ss->epss[s];
            float inv_eps = 1.0f / eps;
            const float* hp = ss->pot[cur][hq];
            float old = ss->pot[cur][q][i];
            float t = 0.f;
#pragma unroll
            for (int it = 0; it < 4; it++) {
                int jj = jg * 4 + it;
                float u = (hp[jj] - Crow[jj]) * inv_eps;
                t += u * fmaf(u, fmaf(u, 0.16666667f, 0.5f), 1.0f);   // expm1
            }
            t += __shfl_xor_sync(0xffffffffu, t, 1);
            t += __shfl_xor_sync(0xffffffffu, t, 2);
            if (jg == 0) {
                float m = t * 0.0625f;
                float l = m * fmaf(m, fmaf(m, 0.33333333f, -0.5f), 1.0f);  // log1p
                ss->pot[cur ^ 1][q][i] = 0.5f * (old - eps * l);
            }
            __syncthreads();
            cur ^= 1;
        }

        {
            const float eps = 0.0025f;
            const float inv_eps = 1.0f / eps;
            const float* hp = ss->pot[cur][hq];
            float t = 0.f;
#pragma unroll
            for (int it = 0; it < 4; it++) {
                int jj = jg * 4 + it;
                float u = (hp[jj] - Crow[jj]) * inv_eps;
                t += u * fmaf(u, fmaf(u, 0.16666667f, 0.5f), 1.0f);
            }
            t += __shfl_xor_sync(0xffffffffu, t, 1);
            t += __shfl_xor_sync(0xffffffffu, t, 2);
            if (jg == 0) {
                float m = t * 0.0625f;
                float l = m * fmaf(m, fmaf(m, 0.33333333f, -0.5f), 1.0f);
                ss->fin[q][i] = -eps * l;
            }
            __syncthreads();
        }
    }

    if (tid == 0) {
        float acc2 = 0.f;
#pragma unroll
        for (int ii = 0; ii < 16; ii++)
            acc2 += (ss->fin[0][ii] - ss->fin[2][ii])
                  + (ss->fin[1][ii] - ss->fin[3][ii]);
        g_partial[pair] = acc2 / 48.0f;      // mean over 16, /3 pairs
        __threadfence();
        unsigned int tk = atomicAdd(&g_ctr, 1);
        if (tk == 2) {
            out[0] = g_partial[0] + g_partial[1] + g_partial[2];
            g_ctr = 0;                       // self-reset for graph replay
        }
    }
}

// ---------------------------------------------------------------------------
extern "C" void kernel_launch(void* const* d_in, const int* in_sizes, int n_in,
                              void* d_out, int out_size)
{
    (void)out_size;
    // Pair the 6 inputs by element count (divergence is symmetric in (x, y)).
    int idx[6] = {0, 1, 2, 3, 4, 5};
    int n = (n_in < 6) ? n_in : 6;
    for (int a = 0; a < n; a++)
        for (int b = a + 1; b < n; b++)
            if (in_sizes[idx[b]] > in_sizes[idx[a]]) {
                int tmp = idx[a]; idx[a] = idx[b]; idx[b] = tmp;
            }

    const float* T[3]; const float* R[3]; int M[3]; int nb[3];
    for (int p = 0; p < 3; p++) {
        T[p] = (const float*)d_in[idx[2 * p]];
        R[p] = (const float*)d_in[idx[2 * p + 1]];
        M[p] = in_sizes[idx[2 * p]] / BROWS;
        int iters = M[p] >> 7;                 // TKI = 128
        nb[p] = (iters + 48) / 49;             // ~49 iters/block, <=296 blocks total
        if (nb[p] < 1) nb[p] = 1;
        if (nb[p] > iters) nb[p] = iters;
    }
    // slot-array safety: total blocks must fit g_bgram (304 slots)
    int tot = nb[0] + nb[1] + nb[2];
    if (tot > 304) { nb[0] -= (tot - 304); if (nb[0] < 1) nb[0] = 1; tot = nb[0] + nb[1] + nb[2]; }

    static int smem_set = 0;
    if (!smem_set) {
        cudaFuncSetAttribute(fused_kernel,
                             cudaFuncAttributeMaxDynamicSharedMemorySize, SMEMB);
        smem_set = 1;
    }

    fused_kernel<<<tot, NTHR, SMEMB>>>(
        T[0], R[0], M[0], nb[0],
        T[1], R[1], M[1], nb[1],
        T[2], R[2], M[2], nb[2],
        (float*)d_out);
}